// round 1
// baseline (speedup 1.0000x reference)
#include <cuda_runtime.h>

#define IN_F   8192
#define OUT_F  8192
#define BATCH  2048

#define ROW_SPLITS 128            // 8192 rows / 128 splits = 64 rows per block
#define ROWS_PER_SPLIT (OUT_F / ROW_SPLITS)
#define COL_TILES 8               // 8192 cols / 8 = 1024 cols per block (256 thr * float4)

// Scratch (fully overwritten every call -> deterministic, no init needed)
__device__ float g_part[ROW_SPLITS * IN_F];   // 4 MB
__device__ float g_colsum[IN_F];
__device__ float g_bias;

// ---------------------------------------------------------------------------
// K1: partial column sums of weight.  grid (COL_TILES, ROW_SPLITS), block 256.
// Each thread owns 4 consecutive columns (float4), accumulates 64 rows.
// ---------------------------------------------------------------------------
__global__ __launch_bounds__(256) void k_colsum_partial(const float* __restrict__ weight)
{
    const int col4 = (blockIdx.x * 256 + threadIdx.x);        // float4 index
    const int col  = col4 * 4;                                 // column base
    const int r0   = blockIdx.y * ROWS_PER_SPLIT;

    float4 acc = make_float4(0.f, 0.f, 0.f, 0.f);
    const float4* wp = reinterpret_cast<const float4*>(weight + (size_t)r0 * IN_F + col);
    const int stride4 = IN_F / 4;                              // float4s per row

    #pragma unroll 8
    for (int r = 0; r < ROWS_PER_SPLIT; ++r) {
        float4 v = wp[(size_t)r * stride4];
        acc.x += v.x; acc.y += v.y; acc.z += v.z; acc.w += v.w;
    }

    reinterpret_cast<float4*>(g_part + (size_t)blockIdx.y * IN_F + col)[0] = acc;
}

// ---------------------------------------------------------------------------
// K2: reduce partials -> g_colsum; block gridDim.x-1 reduces bias -> g_bias.
// grid 33, block 256.
// ---------------------------------------------------------------------------
__global__ __launch_bounds__(256) void k_reduce(const float* __restrict__ bias)
{
    __shared__ float sh[256];
    if (blockIdx.x < 32) {
        const int col = blockIdx.x * 256 + threadIdx.x;
        float s = 0.f;
        #pragma unroll 8
        for (int p = 0; p < ROW_SPLITS; ++p)
            s += g_part[(size_t)p * IN_F + col];
        g_colsum[col] = s;
    } else {
        // bias sum: 8192 elems, 256 threads * 32 each
        float s = 0.f;
        #pragma unroll
        for (int k = 0; k < OUT_F / 256; ++k)
            s += bias[threadIdx.x + k * 256];
        sh[threadIdx.x] = s;
        __syncthreads();
        for (int off = 128; off >= 32; off >>= 1) {
            if (threadIdx.x < off) sh[threadIdx.x] += sh[threadIdx.x + off];
            __syncthreads();
        }
        if (threadIdx.x < 32) {
            float v = sh[threadIdx.x];
            #pragma unroll
            for (int o = 16; o > 0; o >>= 1)
                v += __shfl_down_sync(0xffffffffu, v, o);
            if (threadIdx.x == 0) g_bias = v;
        }
    }
}

// ---------------------------------------------------------------------------
// K3: y[b] = dot(x[b,:], g_colsum) + g_bias.  grid 2048, block 256.
// ---------------------------------------------------------------------------
__global__ __launch_bounds__(256) void k_gemv(const float* __restrict__ x,
                                              float* __restrict__ y)
{
    const int b = blockIdx.x;
    const float4* xp = reinterpret_cast<const float4*>(x + (size_t)b * IN_F);
    const float4* cp = reinterpret_cast<const float4*>(g_colsum);

    float acc = 0.f;
    #pragma unroll
    for (int k = 0; k < (IN_F / 4) / 256; ++k) {            // 8 iters
        const int i4 = k * 256 + threadIdx.x;
        float4 xv = xp[i4];
        float4 cv = cp[i4];
        acc += xv.x * cv.x + xv.y * cv.y + xv.z * cv.z + xv.w * cv.w;
    }

    __shared__ float sh[256];
    sh[threadIdx.x] = acc;
    __syncthreads();
    for (int off = 128; off >= 32; off >>= 1) {
        if (threadIdx.x < off) sh[threadIdx.x] += sh[threadIdx.x + off];
        __syncthreads();
    }
    if (threadIdx.x < 32) {
        float v = sh[threadIdx.x];
        #pragma unroll
        for (int o = 16; o > 0; o >>= 1)
            v += __shfl_down_sync(0xffffffffu, v, o);
        if (threadIdx.x == 0) y[b] = v + g_bias;
    }
}

// ---------------------------------------------------------------------------
extern "C" void kernel_launch(void* const* d_in, const int* in_sizes, int n_in,
                              void* d_out, int out_size)
{
    const float* x      = (const float*)d_in[0];   // (2048, 8192)
    const float* weight = (const float*)d_in[1];   // (8192, 8192)
    const float* bias   = (const float*)d_in[2];   // (8192,)
    float* y            = (float*)d_out;           // (2048, 1)

    dim3 g1(COL_TILES, ROW_SPLITS);
    k_colsum_partial<<<g1, 256>>>(weight);
    k_reduce<<<33, 256>>>(bias);
    k_gemv<<<BATCH, 256>>>(x, y);
}